// round 1
// baseline (speedup 1.0000x reference)
#include <cuda_runtime.h>

#define BB 4
#define NN 4096
#define FF 128
#define ALPHA 0.1f

// ---------------- device scratch (static: no allocations allowed) ----------
__device__ float g_w1[FF], g_w2[FF];
__device__ float g_c[2];
__device__ float g_wh1[BB * NN], g_wh2[BB * NN];
__device__ float g_vp[BB * NN * FF];   // 8 MB
__device__ float g_h [BB * NN * FF];   // 8 MB

__device__ __forceinline__ float leaky(float x) { return fmaxf(x, ALPHA * x); }

// packed f32x2 helpers (sm_100+: fma.rn.f32x2)
__device__ __forceinline__ unsigned long long pack2(float lo, float hi) {
    unsigned long long r;
    asm("mov.b64 %0, {%1, %2};" : "=l"(r) : "r"(__float_as_uint(lo)), "r"(__float_as_uint(hi)));
    return r;
}
__device__ __forceinline__ void unpack2(unsigned long long v, float& lo, float& hi) {
    unsigned int a, b;
    asm("mov.b64 {%0, %1}, %2;" : "=r"(a), "=r"(b) : "l"(v));
    lo = __uint_as_float(a); hi = __uint_as_float(b);
}
__device__ __forceinline__ void fma2(unsigned long long& d, unsigned long long a, unsigned long long b) {
    asm("fma.rn.f32x2 %0, %1, %2, %0;" : "+l"(d) : "l"(a), "l"(b));
}

// ---------------- kernel 1: fold a into the Q/K projections -----------------
// w1 = Wq_w^T @ a[:F], c1 = Wq_b . a[:F];  w2 = Wk_w^T @ a[F:], c2 = Wk_b . a[F:]
__global__ void k_prep(const float* __restrict__ Wq_w, const float* __restrict__ Wq_b,
                       const float* __restrict__ Wk_w, const float* __restrict__ Wk_b,
                       const float* __restrict__ a) {
    int f = threadIdx.x;  // 128 threads
    float s1 = 0.f, s2 = 0.f;
    for (int o = 0; o < FF; o++) {
        s1 += Wq_w[o * FF + f] * a[o];
        s2 += Wk_w[o * FF + f] * a[FF + o];
    }
    g_w1[f] = s1; g_w2[f] = s2;
    if (f == 0) {
        float c1 = 0.f, c2 = 0.f;
        for (int o = 0; o < FF; o++) { c1 += Wq_b[o] * a[o]; c2 += Wk_b[o] * a[FF + o]; }
        g_c[0] = c1; g_c[1] = c2;
    }
}

// ---------------- kernel 2: Wh1 = q@w1 + c1 ; Wh2 = k@w2 + c2 ----------------
__global__ void k_wh(const float* __restrict__ q, const float* __restrict__ k) {
    int warp = threadIdx.x >> 5, lane = threadIdx.x & 31;
    int row = blockIdx.x * 8 + warp;          // [0, 2*B*N)
    const float* src; const float* w; float c; float* dst; int r;
    if (row < BB * NN) { src = q; w = g_w1; c = g_c[0]; dst = g_wh1; r = row; }
    else               { src = k; w = g_w2; c = g_c[1]; dst = g_wh2; r = row - BB * NN; }
    float4 x  = ((const float4*)(src + (size_t)r * FF))[lane];
    float4 ww = ((const float4*)w)[lane];
    float s = x.x * ww.x + x.y * ww.y + x.z * ww.z + x.w * ww.w;
    #pragma unroll
    for (int o = 16; o > 0; o >>= 1) s += __shfl_xor_sync(0xffffffffu, s, o);
    if (lane == 0) dst[r] = s + c;
}

// ---------------- kernel 3/5: (B*N,128) x (128,128)^T GEMM ------------------
// out[i][o] = act( sum_f in[i][f] * W[o][f] + bias[o] )
__global__ void __launch_bounds__(256)
k_gemm128(const float* __restrict__ in, const float* __restrict__ W,
          const float* __restrict__ bias, float* __restrict__ out, int do_leaky) {
    __shared__ __align__(16) float in_s[32][33];
    __shared__ __align__(16) float wt_s[32][132];
    int t = threadIdx.x;
    int i0 = blockIdx.x * 32;
    int w = t >> 5, l = t & 31;          // thread: rows w*4..w*4+3, cols l*4..l*4+3
    float acc[4][4] = {};
    for (int kt = 0; kt < FF; kt += 32) {
        __syncthreads();
        {   // input chunk: 32 rows x 32 f
            int r = t >> 3, f4 = t & 7;
            float4 v = *(const float4*)(in + (size_t)(i0 + r) * FF + kt + f4 * 4);
            in_s[r][f4 * 4 + 0] = v.x; in_s[r][f4 * 4 + 1] = v.y;
            in_s[r][f4 * 4 + 2] = v.z; in_s[r][f4 * 4 + 3] = v.w;
        }
        #pragma unroll
        for (int kk = 0; kk < 4; kk++) {   // W chunk transposed: 128 o x 32 f
            int idx = t + kk * 256;
            int o = idx >> 3, f4 = idx & 7;
            float4 v = *(const float4*)(W + (size_t)o * FF + kt + f4 * 4);
            wt_s[f4 * 4 + 0][o] = v.x; wt_s[f4 * 4 + 1][o] = v.y;
            wt_s[f4 * 4 + 2][o] = v.z; wt_s[f4 * 4 + 3][o] = v.w;
        }
        __syncthreads();
        #pragma unroll
        for (int f = 0; f < 32; f++) {
            float4 wv = *(const float4*)&wt_s[f][l * 4];
            #pragma unroll
            for (int r = 0; r < 4; r++) {
                float iv = in_s[w * 4 + r][f];
                acc[r][0] += iv * wv.x; acc[r][1] += iv * wv.y;
                acc[r][2] += iv * wv.z; acc[r][3] += iv * wv.w;
            }
        }
    }
    float4 bv = make_float4(0.f, 0.f, 0.f, 0.f);
    if (bias) bv = *(const float4*)(bias + l * 4);
    #pragma unroll
    for (int r = 0; r < 4; r++) {
        float4 o4;
        o4.x = acc[r][0] + bv.x; o4.y = acc[r][1] + bv.y;
        o4.z = acc[r][2] + bv.z; o4.w = acc[r][3] + bv.w;
        if (do_leaky) { o4.x = leaky(o4.x); o4.y = leaky(o4.y); o4.z = leaky(o4.z); o4.w = leaky(o4.w); }
        *(float4*)(out + (size_t)(i0 + w * 4 + r) * FF + l * 4) = o4;
    }
}

// ---------------- kernel 4: fused masked softmax-weighted aggregation -------
// For each row i: h_i = sum_j adj_ij * exp(leaky(Wh1_i + Wh2_j)) * vp_j / sum_j(same)
__global__ void __launch_bounds__(256)
k_attn(const int* __restrict__ adj) {
    __shared__ __align__(16) float wh2_s[NN];          // 16 KB
    __shared__ __align__(16) float vp_s[32][128];      // 16 KB
    __shared__ float p_s[32][65];                      // 8.3 KB, conflict-free stores
    __shared__ float wh1_s[64];
    __shared__ float lred[64][9];
    __shared__ float linv_s[64];

    int t = threadIdx.x;
    int b = blockIdx.y;
    int i0 = blockIdx.x * 64;
    int w = t >> 5, l = t & 31;

    // stage Wh2 for the whole batch row + Wh1 for this row tile
    #pragma unroll
    for (int kk = 0; kk < 4; kk++) {
        int idx = t + kk * 256;
        ((float4*)wh2_s)[idx] = ((const float4*)(g_wh2 + b * NN))[idx];
    }
    if (t < 64) wh1_s[t] = g_wh1[b * NN + i0 + t];

    unsigned long long acc[8][2];
    #pragma unroll
    for (int k = 0; k < 8; k++) { acc[k][0] = 0ull; acc[k][1] = 0ull; }
    float rs_a = 0.f, rs_b = 0.f;
    int ra = t >> 3;      // p-phase rows: ra and ra+32
    int jq = t & 7;
    const int* adjbase = adj + ((size_t)b * NN + i0) * NN;

    for (int jt = 0; jt < NN / 32; jt++) {
        int j0 = jt * 32;
        __syncthreads();
        // load vp tile 32 x 128
        #pragma unroll
        for (int kk = 0; kk < 4; kk++) {
            int idx = t + kk * 256;
            int jj = idx >> 5, f4 = idx & 31;
            float4 v = *(const float4*)(g_vp + ((size_t)(b * NN + j0 + jj)) * FF + f4 * 4);
            *(float4*)&vp_s[jj][f4 * 4] = v;
        }
        // masked exp weights for 64 x 32 tile
        {
            float wa = wh1_s[ra], wb = wh1_s[ra + 32];
            int4 ma = *(const int4*)(adjbase + (size_t)ra * NN + j0 + jq * 4);
            int4 mb = *(const int4*)(adjbase + (size_t)(ra + 32) * NN + j0 + jq * 4);
            float h0 = wh2_s[j0 + jq * 4 + 0];
            float h1 = wh2_s[j0 + jq * 4 + 1];
            float h2 = wh2_s[j0 + jq * 4 + 2];
            float h3 = wh2_s[j0 + jq * 4 + 3];
            float a0 = (ma.x > 0) ? __expf(leaky(wa + h0)) : 0.f;
            float a1 = (ma.y > 0) ? __expf(leaky(wa + h1)) : 0.f;
            float a2 = (ma.z > 0) ? __expf(leaky(wa + h2)) : 0.f;
            float a3 = (ma.w > 0) ? __expf(leaky(wa + h3)) : 0.f;
            float b0 = (mb.x > 0) ? __expf(leaky(wb + h0)) : 0.f;
            float b1 = (mb.y > 0) ? __expf(leaky(wb + h1)) : 0.f;
            float b2 = (mb.z > 0) ? __expf(leaky(wb + h2)) : 0.f;
            float b3 = (mb.w > 0) ? __expf(leaky(wb + h3)) : 0.f;
            p_s[jq * 4 + 0][ra] = a0; p_s[jq * 4 + 1][ra] = a1;
            p_s[jq * 4 + 2][ra] = a2; p_s[jq * 4 + 3][ra] = a3;
            p_s[jq * 4 + 0][ra + 32] = b0; p_s[jq * 4 + 1][ra + 32] = b1;
            p_s[jq * 4 + 2][ra + 32] = b2; p_s[jq * 4 + 3][ra + 32] = b3;
            rs_a += (a0 + a1) + (a2 + a3);
            rs_b += (b0 + b1) + (b2 + b3);
        }
        __syncthreads();
        // FMA phase: warp w handles rows w*8..w*8+7, lane l handles cols 4l..4l+3
        #pragma unroll 4
        for (int jj = 0; jj < 32; jj++) {
            float4 v4 = *(const float4*)&vp_s[jj][l * 4];
            unsigned long long v01 = pack2(v4.x, v4.y);
            unsigned long long v23 = pack2(v4.z, v4.w);
            #pragma unroll
            for (int k = 0; k < 8; k++) {
                float p = p_s[jj][w * 8 + k];
                unsigned long long pp = pack2(p, p);
                fma2(acc[k][0], pp, v01);
                fma2(acc[k][1], pp, v23);
            }
        }
    }

    // reduce per-row normalizers
    lred[ra][jq] = rs_a;
    lred[ra + 32][jq] = rs_b;
    __syncthreads();
    if (t < 64) {
        float s = 0.f;
        #pragma unroll
        for (int q8 = 0; q8 < 8; q8++) s += lred[t][q8];
        linv_s[t] = 1.0f / s;
    }
    __syncthreads();

    #pragma unroll
    for (int k = 0; k < 8; k++) {
        int row = w * 8 + k;
        float sinv = linv_s[row];
        float x, y, z, u;
        unpack2(acc[k][0], x, y);
        unpack2(acc[k][1], z, u);
        float4 o4 = make_float4(x * sinv, y * sinv, z * sinv, u * sinv);
        *(float4*)(g_h + ((size_t)(b * NN + i0 + row)) * FF + l * 4) = o4;
    }
}

// ---------------- launch -----------------------------------------------------
extern "C" void kernel_launch(void* const* d_in, const int* in_sizes, int n_in,
                              void* d_out, int out_size) {
    const float* q    = (const float*)d_in[0];
    const float* k    = (const float*)d_in[1];
    const float* v    = (const float*)d_in[2];
    const int*   adj  = (const int*)  d_in[3];
    const float* Wq_w = (const float*)d_in[4];
    const float* Wq_b = (const float*)d_in[5];
    const float* Wk_w = (const float*)d_in[6];
    const float* Wk_b = (const float*)d_in[7];
    const float* Wv_w = (const float*)d_in[8];
    const float* Wv_b = (const float*)d_in[9];
    const float* a    = (const float*)d_in[10];
    const float* Wo_w = (const float*)d_in[11];
    float* out = (float*)d_out;

    void* vp_ptr = nullptr;  cudaGetSymbolAddress(&vp_ptr, g_vp);
    void* h_ptr  = nullptr;  cudaGetSymbolAddress(&h_ptr,  g_h);

    k_prep<<<1, 128>>>(Wq_w, Wq_b, Wk_w, Wk_b, a);
    k_wh<<<(2 * BB * NN) / 8, 256>>>(q, k);
    k_gemm128<<<BB * NN / 32, 256>>>(v, Wv_w, Wv_b, (float*)vp_ptr, 0);
    {
        dim3 grid(NN / 64, BB);
        k_attn<<<grid, 256>>>(adj);
    }
    k_gemm128<<<BB * NN / 32, 256>>>((const float*)h_ptr, Wo_w, nullptr, out, 1);
}

// round 3
// speedup vs baseline: 1.4473x; 1.4473x over previous
#include <cuda_runtime.h>
#include <cuda_fp16.h>
#include <cstdint>

#define BB 4
#define NN 4096
#define FF 128
#define ALPHA 0.1f
#define KC 64

// ---------------- device scratch ----------------
__device__ float g_w1[FF], g_w2[FF], g_c[2];
__device__ float g_wh1[BB * NN], g_wh2[BB * NN];
__device__ float g_h[BB * NN * FF];                      // 8 MB
__device__ __align__(16) __half g_vph[BB * NN * FF];     // 4 MB  [b][j][f] fp16 hi
__device__ __align__(16) __half g_vpl[BB * NN * FF];     // 4 MB  fp16 lo residual

__device__ __forceinline__ float leaky(float x) { return fmaxf(x, ALPHA * x); }

// ---------------- mma.sync helpers (sm_80+, valid on sm_103 base) ----------
__device__ __forceinline__ void mma16816(float* d, const uint32_t* a, const uint32_t* b) {
    asm volatile("mma.sync.aligned.m16n8k16.row.col.f32.f16.f16.f32 "
        "{%0,%1,%2,%3},{%4,%5,%6,%7},{%8,%9},{%0,%1,%2,%3};"
        : "+f"(d[0]), "+f"(d[1]), "+f"(d[2]), "+f"(d[3])
        : "r"(a[0]), "r"(a[1]), "r"(a[2]), "r"(a[3]), "r"(b[0]), "r"(b[1]));
}
__device__ __forceinline__ void ldsm_x4(uint32_t* r, uint32_t addr) {
    asm volatile("ldmatrix.sync.aligned.m8n8.x4.shared.b16 {%0,%1,%2,%3},[%4];"
        : "=r"(r[0]), "=r"(r[1]), "=r"(r[2]), "=r"(r[3]) : "r"(addr));
}
__device__ __forceinline__ void ldsm_x4_t(uint32_t* r, uint32_t addr) {
    asm volatile("ldmatrix.sync.aligned.m8n8.x4.trans.shared.b16 {%0,%1,%2,%3},[%4];"
        : "=r"(r[0]), "=r"(r[1]), "=r"(r[2]), "=r"(r[3]) : "r"(addr));
}
__device__ __forceinline__ uint32_t smem_u32(const void* p) {
    uint32_t a;
    asm("{ .reg .u64 t; cvta.to.shared.u64 t, %1; cvt.u32.u64 %0, t; }" : "=r"(a) : "l"(p));
    return a;
}
__device__ __forceinline__ uint32_t h2u(__half2 h) { return *(uint32_t*)&h; }

// ---------------- kernel 1: fold a into Q/K projections ----------------
__global__ void k_prep(const float* __restrict__ Wq_w, const float* __restrict__ Wq_b,
                       const float* __restrict__ Wk_w, const float* __restrict__ Wk_b,
                       const float* __restrict__ a) {
    int f = threadIdx.x;
    float s1 = 0.f, s2 = 0.f;
    for (int o = 0; o < FF; o++) {
        s1 += Wq_w[o * FF + f] * a[o];
        s2 += Wk_w[o * FF + f] * a[FF + o];
    }
    g_w1[f] = s1; g_w2[f] = s2;
    if (f == 0) {
        float c1 = 0.f, c2 = 0.f;
        for (int o = 0; o < FF; o++) { c1 += Wq_b[o] * a[o]; c2 += Wk_b[o] * a[FF + o]; }
        g_c[0] = c1; g_c[1] = c2;
    }
}

// ---------------- kernel 2: Wh1/Wh2 ----------------
__global__ void k_wh(const float* __restrict__ q, const float* __restrict__ k) {
    int warp = threadIdx.x >> 5, lane = threadIdx.x & 31;
    int row = blockIdx.x * 8 + warp;
    const float* src; const float* w; float c; float* dst; int r;
    if (row < BB * NN) { src = q; w = g_w1; c = g_c[0]; dst = g_wh1; r = row; }
    else               { src = k; w = g_w2; c = g_c[1]; dst = g_wh2; r = row - BB * NN; }
    float4 x  = ((const float4*)(src + (size_t)r * FF))[lane];
    float4 ww = ((const float4*)w)[lane];
    float s = x.x * ww.x + x.y * ww.y + x.z * ww.z + x.w * ww.w;
    #pragma unroll
    for (int o = 16; o > 0; o >>= 1) s += __shfl_xor_sync(0xffffffffu, s, o);
    if (lane == 0) dst[r] = s + c;
}

// ---------------- kernel 3/5: 128x128 projection GEMM ----------------
// mode 0: out_f32 = leaky(in@W^T)          (output projection)
// mode 1: g_vph/g_vpl = fp16 hi/lo of in@W^T + bias   (V projection)
__global__ void __launch_bounds__(256)
k_gemm128(const float* __restrict__ in, const float* __restrict__ W,
          const float* __restrict__ bias, float* __restrict__ outf, int mode) {
    __shared__ __align__(16) float in_s[32][33];
    __shared__ __align__(16) float wt_s[32][132];
    int t = threadIdx.x;
    int i0 = blockIdx.x * 32;
    int w = t >> 5, l = t & 31;
    float acc[4][4] = {};
    for (int kt = 0; kt < FF; kt += 32) {
        __syncthreads();
        {
            int r = t >> 3, f4 = t & 7;
            float4 v = *(const float4*)(in + (size_t)(i0 + r) * FF + kt + f4 * 4);
            in_s[r][f4 * 4 + 0] = v.x; in_s[r][f4 * 4 + 1] = v.y;
            in_s[r][f4 * 4 + 2] = v.z; in_s[r][f4 * 4 + 3] = v.w;
        }
        #pragma unroll
        for (int kk = 0; kk < 4; kk++) {
            int idx = t + kk * 256;
            int o = idx >> 3, f4 = idx & 7;
            float4 v = *(const float4*)(W + (size_t)o * FF + kt + f4 * 4);
            wt_s[f4 * 4 + 0][o] = v.x; wt_s[f4 * 4 + 1][o] = v.y;
            wt_s[f4 * 4 + 2][o] = v.z; wt_s[f4 * 4 + 3][o] = v.w;
        }
        __syncthreads();
        #pragma unroll
        for (int f = 0; f < 32; f++) {
            float4 wv = *(const float4*)&wt_s[f][l * 4];
            #pragma unroll
            for (int r = 0; r < 4; r++) {
                float iv = in_s[w * 4 + r][f];
                acc[r][0] += iv * wv.x; acc[r][1] += iv * wv.y;
                acc[r][2] += iv * wv.z; acc[r][3] += iv * wv.w;
            }
        }
    }
    float4 bv = make_float4(0.f, 0.f, 0.f, 0.f);
    if (mode == 1) bv = *(const float4*)(bias + l * 4);
    #pragma unroll
    for (int r = 0; r < 4; r++) {
        float4 o4;
        o4.x = acc[r][0] + bv.x; o4.y = acc[r][1] + bv.y;
        o4.z = acc[r][2] + bv.z; o4.w = acc[r][3] + bv.w;
        size_t base = (size_t)(i0 + w * 4 + r) * FF + l * 4;
        if (mode == 0) {
            o4.x = leaky(o4.x); o4.y = leaky(o4.y); o4.z = leaky(o4.z); o4.w = leaky(o4.w);
            *(float4*)(outf + base) = o4;
        } else {
            __half2 h01 = __floats2half2_rn(o4.x, o4.y);
            __half2 h23 = __floats2half2_rn(o4.z, o4.w);
            float2 f01 = __half22float2(h01), f23 = __half22float2(h23);
            __half2 l01 = __floats2half2_rn(o4.x - f01.x, o4.y - f01.y);
            __half2 l23 = __floats2half2_rn(o4.z - f23.x, o4.w - f23.y);
            *(uint2*)(g_vph + base) = make_uint2(h2u(h01), h2u(h23));
            *(uint2*)(g_vpl + base) = make_uint2(h2u(l01), h2u(l23));
        }
    }
}

// ---------------- kernel 4: fused masked softmax-agg via mma.sync ----------
// smem layout (bytes)
#define PH_OFF 0
#define PL_OFF 18432
#define VH_OFF 36864
#define VL_OFF 54272
#define RS_OFF 71680
#define IV_OFF 72704
#define SM_TOTAL 73216
#define PSTRIDE 144    // 72 halves per P row
#define VSTRIDE 272    // 136 halves per V row

__global__ void __launch_bounds__(256, 1)
k_attn_mma(const int* __restrict__ adj) {
    extern __shared__ char sm[];
    int t = threadIdx.x;
    int lane = t & 31, wid = t >> 5;
    int b = blockIdx.y;
    int it0 = blockIdx.x * 128;

    int mwarp = (wid >> 1) * 32;     // 4 warps down M
    int nwarp = (wid & 1) * 64;      // 2 warps across N

    uint32_t sbase = smem_u32(sm);

    // ldmatrix lane bases
    uint32_t aoffH = sbase + PH_OFF + (uint32_t)(mwarp + (lane & 15)) * PSTRIDE + (lane >> 4) * 16;
    uint32_t aoffL = aoffH + (PL_OFF - PH_OFF);
    uint32_t boffH = sbase + VH_OFF + (uint32_t)(lane & 15) * VSTRIDE + (nwarp + (lane >> 4) * 8) * 2;
    uint32_t boffL = boffH + (VL_OFF - VH_OFF);

    // P-gen mapping: thread -> (row, 32-wide j half)
    int prow = t >> 1;
    int jh = (t & 1) * 32;
    float wa = g_wh1[b * NN + it0 + prow];
    const int* adjr = adj + ((size_t)(b * NN + it0 + prow)) * NN + jh;
    const float* wh2r = g_wh2 + b * NN + jh;
    const __half* vph = g_vph + (size_t)b * NN * FF;
    const __half* vpl = g_vpl + (size_t)b * NN * FF;
    char* pdstH = sm + PH_OFF + prow * PSTRIDE + jh * 2;
    char* pdstL = sm + PL_OFF + prow * PSTRIDE + jh * 2;

    float acc[2][8][4];
    #pragma unroll
    for (int mi = 0; mi < 2; mi++)
        #pragma unroll
        for (int n8 = 0; n8 < 8; n8++)
            #pragma unroll
            for (int x = 0; x < 4; x++) acc[mi][n8][x] = 0.f;
    float rs = 0.f;

    for (int c = 0; c < NN / KC; c++) {
        int j0 = c * KC;
        __syncthreads();
        // ---- V tile fill: 64 rows x 128 halves, hi & lo ----
        #pragma unroll
        for (int kk = 0; kk < 4; kk++) {
            int idx = t + kk * 256;
            int r = idx >> 4, s = idx & 15;
            *(uint4*)(sm + VH_OFF + r * VSTRIDE + s * 16) =
                *(const uint4*)(vph + (size_t)(j0 + r) * FF + s * 8);
            *(uint4*)(sm + VL_OFF + r * VSTRIDE + s * 16) =
                *(const uint4*)(vpl + (size_t)(j0 + r) * FF + s * 8);
        }
        // ---- P tile: exp(leaky(wh1+wh2)) masked, fp32 -> hi/lo fp16 ----
        #pragma unroll
        for (int qq = 0; qq < 8; qq++) {
            int4   m = *(const int4*)  (adjr + j0 + qq * 4);
            float4 e = *(const float4*)(wh2r + j0 + qq * 4);
            float p0 = (m.x > 0) ? __expf(leaky(wa + e.x)) : 0.f;
            float p1 = (m.y > 0) ? __expf(leaky(wa + e.y)) : 0.f;
            float p2 = (m.z > 0) ? __expf(leaky(wa + e.z)) : 0.f;
            float p3 = (m.w > 0) ? __expf(leaky(wa + e.w)) : 0.f;
            rs += (p0 + p1) + (p2 + p3);
            __half2 h01 = __floats2half2_rn(p0, p1);
            __half2 h23 = __floats2half2_rn(p2, p3);
            float2 f01 = __half22float2(h01), f23 = __half22float2(h23);
            __half2 l01 = __floats2half2_rn(p0 - f01.x, p1 - f01.y);
            __half2 l23 = __floats2half2_rn(p2 - f23.x, p3 - f23.y);
            *(uint2*)(pdstH + qq * 8) = make_uint2(h2u(h01), h2u(h23));
            *(uint2*)(pdstL + qq * 8) = make_uint2(h2u(l01), h2u(l23));
        }
        __syncthreads();
        // ---- MMA: 4 k16 steps, 3 precision passes ----
        #pragma unroll
        for (int kk = 0; kk < 4; kk++) {
            uint32_t ah[2][4], al[2][4];
            ldsm_x4(ah[0], aoffH + kk * 32);
            ldsm_x4(ah[1], aoffH + 16 * PSTRIDE + kk * 32);
            ldsm_x4(al[0], aoffL + kk * 32);
            ldsm_x4(al[1], aoffL + 16 * PSTRIDE + kk * 32);
            #pragma unroll
            for (int nb = 0; nb < 4; nb++) {
                uint32_t bh[4], bl[4];
                ldsm_x4_t(bh, boffH + kk * 16 * VSTRIDE + nb * 32);
                ldsm_x4_t(bl, boffL + kk * 16 * VSTRIDE + nb * 32);
                #pragma unroll
                for (int mi = 0; mi < 2; mi++) {
                    mma16816(acc[mi][nb * 2 + 0], ah[mi], bh + 0);
                    mma16816(acc[mi][nb * 2 + 1], ah[mi], bh + 2);
                    mma16816(acc[mi][nb * 2 + 0], al[mi], bh + 0);
                    mma16816(acc[mi][nb * 2 + 1], al[mi], bh + 2);
                    mma16816(acc[mi][nb * 2 + 0], ah[mi], bl + 0);
                    mma16816(acc[mi][nb * 2 + 1], ah[mi], bl + 2);
                }
            }
        }
    }

    // ---- normalizers ----
    __syncthreads();
    ((float*)(sm + RS_OFF))[t] = rs;
    __syncthreads();
    if (t < 128) {
        float* rss = (float*)(sm + RS_OFF);
        ((float*)(sm + IV_OFF))[t] = 1.0f / (rss[2 * t] + rss[2 * t + 1]);
    }
    __syncthreads();
    const float* inv = (const float*)(sm + IV_OFF);

    // ---- write h ----
    #pragma unroll
    for (int mi = 0; mi < 2; mi++) {
        int r0 = mwarp + mi * 16 + (lane >> 2);
        float iv0 = inv[r0], iv1 = inv[r0 + 8];
        #pragma unroll
        for (int n8 = 0; n8 < 8; n8++) {
            int col = nwarp + n8 * 8 + (lane & 3) * 2;
            float2 v0 = make_float2(acc[mi][n8][0] * iv0, acc[mi][n8][1] * iv0);
            float2 v1 = make_float2(acc[mi][n8][2] * iv1, acc[mi][n8][3] * iv1);
            *(float2*)(g_h + (size_t)(b * NN + it0 + r0) * FF + col) = v0;
            *(float2*)(g_h + (size_t)(b * NN + it0 + r0 + 8) * FF + col) = v1;
        }
    }
}

// ---------------- launch ----------------
extern "C" void kernel_launch(void* const* d_in, const int* in_sizes, int n_in,
                              void* d_out, int out_size) {
    const float* q    = (const float*)d_in[0];
    const float* k    = (const float*)d_in[1];
    const float* v    = (const float*)d_in[2];
    const int*   adj  = (const int*)  d_in[3];
    const float* Wq_w = (const float*)d_in[4];
    const float* Wq_b = (const float*)d_in[5];
    const float* Wk_w = (const float*)d_in[6];
    const float* Wk_b = (const float*)d_in[7];
    const float* Wv_w = (const float*)d_in[8];
    const float* Wv_b = (const float*)d_in[9];
    const float* a    = (const float*)d_in[10];
    const float* Wo_w = (const float*)d_in[11];
    float* out = (float*)d_out;

    void* h_ptr = nullptr;
    cudaGetSymbolAddress(&h_ptr, g_h);

    cudaFuncSetAttribute(k_attn_mma, cudaFuncAttributeMaxDynamicSharedMemorySize, SM_TOTAL);

    k_prep<<<1, 128>>>(Wq_w, Wq_b, Wk_w, Wk_b, a);
    k_wh<<<(2 * BB * NN) / 8, 256>>>(q, k);
    k_gemm128<<<BB * NN / 32, 256>>>(v, Wv_w, Wv_b, nullptr, 1);
    {
        dim3 grid(NN / 128, BB);
        k_attn_mma<<<grid, 256, SM_TOTAL>>>(adj);
    }
    k_gemm128<<<BB * NN / 32, 256>>>((const float*)h_ptr, Wo_w, nullptr, out, 0);
}

// round 4
// speedup vs baseline: 1.5204x; 1.0505x over previous
#include <cuda_runtime.h>
#include <cuda_fp16.h>
#include <cstdint>

#define BB 4
#define NN 4096
#define FF 128
#define ALPHA 0.1f
#define KC 64

// ---------------- device scratch ----------------
__device__ float g_w1[FF], g_w2[FF], g_c[2];
__device__ float g_wh1[BB * NN], g_wh2[BB * NN];
__device__ float g_h[BB * NN * FF];                      // 8 MB
__device__ __align__(16) __half g_vph[BB * NN * FF];     // 4 MB  [b][j][f] fp16
__device__ __align__(16) __half g_vpl[BB * NN * FF];     // kept for symbol compat (unused)

__device__ __forceinline__ float leaky(float x) { return fmaxf(x, ALPHA * x); }

// ---------------- mma.sync helpers ----------------
__device__ __forceinline__ void mma16816(float* d, const uint32_t* a, const uint32_t* b) {
    asm volatile("mma.sync.aligned.m16n8k16.row.col.f32.f16.f16.f32 "
        "{%0,%1,%2,%3},{%4,%5,%6,%7},{%8,%9},{%0,%1,%2,%3};"
        : "+f"(d[0]), "+f"(d[1]), "+f"(d[2]), "+f"(d[3])
        : "r"(a[0]), "r"(a[1]), "r"(a[2]), "r"(a[3]), "r"(b[0]), "r"(b[1]));
}
__device__ __forceinline__ void ldsm_x4(uint32_t* r, uint32_t addr) {
    asm volatile("ldmatrix.sync.aligned.m8n8.x4.shared.b16 {%0,%1,%2,%3},[%4];"
        : "=r"(r[0]), "=r"(r[1]), "=r"(r[2]), "=r"(r[3]) : "r"(addr));
}
__device__ __forceinline__ void ldsm_x4_t(uint32_t* r, uint32_t addr) {
    asm volatile("ldmatrix.sync.aligned.m8n8.x4.trans.shared.b16 {%0,%1,%2,%3},[%4];"
        : "=r"(r[0]), "=r"(r[1]), "=r"(r[2]), "=r"(r[3]) : "r"(addr));
}
__device__ __forceinline__ uint32_t smem_u32(const void* p) {
    uint32_t a;
    asm("{ .reg .u64 t; cvta.to.shared.u64 t, %1; cvt.u32.u64 %0, t; }" : "=r"(a) : "l"(p));
    return a;
}
__device__ __forceinline__ void cp16(uint32_t dst, const void* src) {
    asm volatile("cp.async.cg.shared.global [%0], [%1], 16;" :: "r"(dst), "l"(src) : "memory");
}
#define CP_COMMIT() asm volatile("cp.async.commit_group;" ::: "memory")
#define CP_WAIT0()  asm volatile("cp.async.wait_group 0;" ::: "memory")
__device__ __forceinline__ uint32_t h2u(__half2 h) { return *(uint32_t*)&h; }

// ---------------- kernel 1: fold a into Q/K projections ----------------
__global__ void k_prep(const float* __restrict__ Wq_w, const float* __restrict__ Wq_b,
                       const float* __restrict__ Wk_w, const float* __restrict__ Wk_b,
                       const float* __restrict__ a) {
    int f = threadIdx.x;
    float s1 = 0.f, s2 = 0.f;
    for (int o = 0; o < FF; o++) {
        s1 += Wq_w[o * FF + f] * a[o];
        s2 += Wk_w[o * FF + f] * a[FF + o];
    }
    g_w1[f] = s1; g_w2[f] = s2;
    if (f == 0) {
        float c1 = 0.f, c2 = 0.f;
        for (int o = 0; o < FF; o++) { c1 += Wq_b[o] * a[o]; c2 += Wk_b[o] * a[FF + o]; }
        g_c[0] = c1; g_c[1] = c2;
    }
}

// ---------------- kernel 2: Wh1/Wh2 ----------------
__global__ void k_wh(const float* __restrict__ q, const float* __restrict__ k) {
    int warp = threadIdx.x >> 5, lane = threadIdx.x & 31;
    int row = blockIdx.x * 8 + warp;
    const float* src; const float* w; float c; float* dst; int r;
    if (row < BB * NN) { src = q; w = g_w1; c = g_c[0]; dst = g_wh1; r = row; }
    else               { src = k; w = g_w2; c = g_c[1]; dst = g_wh2; r = row - BB * NN; }
    float4 x  = ((const float4*)(src + (size_t)r * FF))[lane];
    float4 ww = ((const float4*)w)[lane];
    float s = x.x * ww.x + x.y * ww.y + x.z * ww.z + x.w * ww.w;
    #pragma unroll
    for (int o = 16; o > 0; o >>= 1) s += __shfl_xor_sync(0xffffffffu, s, o);
    if (lane == 0) dst[r] = s + c;
}

// ---------------- kernel 3/5: 128x128 projection GEMM ----------------
__global__ void __launch_bounds__(256)
k_gemm128(const float* __restrict__ in, const float* __restrict__ W,
          const float* __restrict__ bias, float* __restrict__ outf, int mode) {
    __shared__ __align__(16) float in_s[32][33];
    __shared__ __align__(16) float wt_s[32][132];
    int t = threadIdx.x;
    int i0 = blockIdx.x * 32;
    int w = t >> 5, l = t & 31;
    float acc[4][4] = {};
    for (int kt = 0; kt < FF; kt += 32) {
        __syncthreads();
        {
            int r = t >> 3, f4 = t & 7;
            float4 v = *(const float4*)(in + (size_t)(i0 + r) * FF + kt + f4 * 4);
            in_s[r][f4 * 4 + 0] = v.x; in_s[r][f4 * 4 + 1] = v.y;
            in_s[r][f4 * 4 + 2] = v.z; in_s[r][f4 * 4 + 3] = v.w;
        }
        #pragma unroll
        for (int kk = 0; kk < 4; kk++) {
            int idx = t + kk * 256;
            int o = idx >> 3, f4 = idx & 7;
            float4 v = *(const float4*)(W + (size_t)o * FF + kt + f4 * 4);
            wt_s[f4 * 4 + 0][o] = v.x; wt_s[f4 * 4 + 1][o] = v.y;
            wt_s[f4 * 4 + 2][o] = v.z; wt_s[f4 * 4 + 3][o] = v.w;
        }
        __syncthreads();
        #pragma unroll
        for (int f = 0; f < 32; f++) {
            float4 wv = *(const float4*)&wt_s[f][l * 4];
            #pragma unroll
            for (int r = 0; r < 4; r++) {
                float iv = in_s[w * 4 + r][f];
                acc[r][0] += iv * wv.x; acc[r][1] += iv * wv.y;
                acc[r][2] += iv * wv.z; acc[r][3] += iv * wv.w;
            }
        }
    }
    float4 bv = make_float4(0.f, 0.f, 0.f, 0.f);
    if (mode == 1) bv = *(const float4*)(bias + l * 4);
    #pragma unroll
    for (int r = 0; r < 4; r++) {
        float4 o4;
        o4.x = acc[r][0] + bv.x; o4.y = acc[r][1] + bv.y;
        o4.z = acc[r][2] + bv.z; o4.w = acc[r][3] + bv.w;
        size_t base = (size_t)(i0 + w * 4 + r) * FF + l * 4;
        if (mode == 0) {
            o4.x = leaky(o4.x); o4.y = leaky(o4.y); o4.z = leaky(o4.z); o4.w = leaky(o4.w);
            *(float4*)(outf + base) = o4;
        } else {
            __half2 h01 = __floats2half2_rn(o4.x, o4.y);
            __half2 h23 = __floats2half2_rn(o4.z, o4.w);
            *(uint2*)(g_vph + base) = make_uint2(h2u(h01), h2u(h23));
        }
    }
}

// ---------------- kernel 4: pipelined masked softmax-agg via mma.sync ------
// smem byte offsets (double buffered)
#define PH_BASE 0            // P hi: 2 x 18432
#define PL_BASE 36864        // P lo: 2 x 18432
#define VH_BASE 73728        // V hi: 2 x 17408
#define RS_OFF  108544
#define IV_OFF  109568
#define SM_TOTAL 110080
#define PSTRIDE 144
#define VSTRIDE 272
#define PBUF 18432
#define VBUF 17408

__global__ void __launch_bounds__(256, 1)
k_attn_mma(const int* __restrict__ adj) {
    extern __shared__ char sm[];
    int t = threadIdx.x;
    int lane = t & 31, wid = t >> 5;
    int b = blockIdx.y;
    int it0 = blockIdx.x * 128;

    int mwarp = (wid >> 1) * 32;
    int nwarp = (wid & 1) * 64;

    uint32_t sbase = smem_u32(sm);
    uint32_t aoffH = sbase + PH_BASE + (uint32_t)(mwarp + (lane & 15)) * PSTRIDE + (lane >> 4) * 16;
    uint32_t aoffL = aoffH + (PL_BASE - PH_BASE);
    uint32_t boffH = sbase + VH_BASE + (uint32_t)(lane & 15) * VSTRIDE + (nwarp + (lane >> 4) * 8) * 2;

    // P-gen mapping
    int prow = t >> 1;
    int jh = (t & 1) * 32;
    float wa = g_wh1[b * NN + it0 + prow];
    const int* adjr = adj + ((size_t)(b * NN + it0 + prow)) * NN + jh;
    const float* wh2r = g_wh2 + b * NN + jh;
    const __half* vph = g_vph + (size_t)b * NN * FF;
    char* pdstH = sm + PH_BASE + prow * PSTRIDE + jh * 2;
    char* pdstL = sm + PL_BASE + prow * PSTRIDE + jh * 2;

    // V cp.async mapping: 4 x 16B per thread per tile
    int vr = t >> 2, vs4 = (t & 3) * 4;   // 4 consecutive 16B chunks per thread
    uint32_t vdst = sbase + VH_BASE + vr * VSTRIDE + vs4 * 16;
    const __half* vsrc0 = vph + (size_t)vr * FF + vs4 * 8;

    float acc[2][8][4];
    #pragma unroll
    for (int mi = 0; mi < 2; mi++)
        #pragma unroll
        for (int n8 = 0; n8 < 8; n8++)
            #pragma unroll
            for (int x = 0; x < 4; x++) acc[mi][n8][x] = 0.f;
    float rs = 0.f;

    uint2 hiR[8], loR[8];

    // ---- P generation into registers for chunk at j0 ----
    auto genP = [&](int j0) {
        #pragma unroll
        for (int qq = 0; qq < 8; qq++) {
            int4   m = *(const int4*)  (adjr + j0 + qq * 4);
            float4 e = *(const float4*)(wh2r + j0 + qq * 4);
            float p0 = (m.x > 0) ? __expf(leaky(wa + e.x)) : 0.f;
            float p1 = (m.y > 0) ? __expf(leaky(wa + e.y)) : 0.f;
            float p2 = (m.z > 0) ? __expf(leaky(wa + e.z)) : 0.f;
            float p3 = (m.w > 0) ? __expf(leaky(wa + e.w)) : 0.f;
            rs += (p0 + p1) + (p2 + p3);
            __half2 h01 = __floats2half2_rn(p0, p1);
            __half2 h23 = __floats2half2_rn(p2, p3);
            float2 f01 = __half22float2(h01), f23 = __half22float2(h23);
            __half2 l01 = __floats2half2_rn(p0 - f01.x, p1 - f01.y);
            __half2 l23 = __floats2half2_rn(p2 - f23.x, p3 - f23.y);
            hiR[qq] = make_uint2(h2u(h01), h2u(h23));
            loR[qq] = make_uint2(h2u(l01), h2u(l23));
        }
    };
    auto storeP = [&](int buf) {
        char* dh = pdstH + buf * PBUF;
        char* dl = pdstL + buf * PBUF;
        #pragma unroll
        for (int qq = 0; qq < 8; qq++) {
            *(uint2*)(dh + qq * 8) = hiR[qq];
            *(uint2*)(dl + qq * 8) = loR[qq];
        }
    };
    auto loadV = [&](int buf, int j0) {
        const __half* s = vsrc0 + (size_t)j0 * FF;
        uint32_t d = vdst + buf * VBUF;
        #pragma unroll
        for (int kk = 0; kk < 4; kk++)
            cp16(d + kk * 16, s + kk * 8);
        CP_COMMIT();
    };

    // ---- prologue: stage chunk 0 ----
    loadV(0, 0);
    genP(0);
    storeP(0);
    CP_WAIT0();
    __syncthreads();

    for (int c = 0; c < NN / KC; c++) {
        int buf = c & 1, nbuf = buf ^ 1;
        bool has_next = (c + 1) < (NN / KC);
        if (has_next) {
            loadV(nbuf, (c + 1) * KC);
            genP((c + 1) * KC);
        }
        // ---- MMA on buffer `buf` ----
        uint32_t pb = aoffH + buf * PBUF;
        uint32_t plb = aoffL + buf * PBUF;
        uint32_t vb = boffH + buf * VBUF;
        #pragma unroll
        for (int kk = 0; kk < 4; kk++) {
            uint32_t ah[2][4], al[2][4];
            ldsm_x4(ah[0], pb + kk * 32);
            ldsm_x4(ah[1], pb + 16 * PSTRIDE + kk * 32);
            ldsm_x4(al[0], plb + kk * 32);
            ldsm_x4(al[1], plb + 16 * PSTRIDE + kk * 32);
            #pragma unroll
            for (int nb = 0; nb < 4; nb++) {
                uint32_t bh[4];
                ldsm_x4_t(bh, vb + kk * 16 * VSTRIDE + nb * 32);
                #pragma unroll
                for (int mi = 0; mi < 2; mi++) {
                    mma16816(acc[mi][nb * 2 + 0], ah[mi], bh + 0);
                    mma16816(acc[mi][nb * 2 + 1], ah[mi], bh + 2);
                    mma16816(acc[mi][nb * 2 + 0], al[mi], bh + 0);
                    mma16816(acc[mi][nb * 2 + 1], al[mi], bh + 2);
                }
            }
        }
        if (has_next) storeP(nbuf);
        CP_WAIT0();
        __syncthreads();
    }

    // ---- normalizers ----
    ((float*)(sm + RS_OFF))[t] = rs;
    __syncthreads();
    if (t < 128) {
        float* rss = (float*)(sm + RS_OFF);
        ((float*)(sm + IV_OFF))[t] = 1.0f / (rss[2 * t] + rss[2 * t + 1]);
    }
    __syncthreads();
    const float* inv = (const float*)(sm + IV_OFF);

    // ---- write h ----
    #pragma unroll
    for (int mi = 0; mi < 2; mi++) {
        int r0 = mwarp + mi * 16 + (lane >> 2);
        float iv0 = inv[r0], iv1 = inv[r0 + 8];
        #pragma unroll
        for (int n8 = 0; n8 < 8; n8++) {
            int col = nwarp + n8 * 8 + (lane & 3) * 2;
            float2 v0 = make_float2(acc[mi][n8][0] * iv0, acc[mi][n8][1] * iv0);
            float2 v1 = make_float2(acc[mi][n8][2] * iv1, acc[mi][n8][3] * iv1);
            *(float2*)(g_h + (size_t)(b * NN + it0 + r0) * FF + col) = v0;
            *(float2*)(g_h + (size_t)(b * NN + it0 + r0 + 8) * FF + col) = v1;
        }
    }
}

// ---------------- launch ----------------
extern "C" void kernel_launch(void* const* d_in, const int* in_sizes, int n_in,
                              void* d_out, int out_size) {
    const float* q    = (const float*)d_in[0];
    const float* k    = (const float*)d_in[1];
    const float* v    = (const float*)d_in[2];
    const int*   adj  = (const int*)  d_in[3];
    const float* Wq_w = (const float*)d_in[4];
    const float* Wq_b = (const float*)d_in[5];
    const float* Wk_w = (const float*)d_in[6];
    const float* Wk_b = (const float*)d_in[7];
    const float* Wv_w = (const float*)d_in[8];
    const float* Wv_b = (const float*)d_in[9];
    const float* a    = (const float*)d_in[10];
    const float* Wo_w = (const float*)d_in[11];
    float* out = (float*)d_out;

    void* h_ptr = nullptr;
    cudaGetSymbolAddress(&h_ptr, g_h);

    cudaFuncSetAttribute(k_attn_mma, cudaFuncAttributeMaxDynamicSharedMemorySize, SM_TOTAL);

    k_prep<<<1, 128>>>(Wq_w, Wq_b, Wk_w, Wk_b, a);
    k_wh<<<(2 * BB * NN) / 8, 256>>>(q, k);
    k_gemm128<<<BB * NN / 32, 256>>>(v, Wv_w, Wv_b, nullptr, 1);
    {
        dim3 grid(NN / 128, BB);
        k_attn_mma<<<grid, 256, SM_TOTAL>>>(adj);
    }
    k_gemm128<<<BB * NN / 32, 256>>>((const float*)h_ptr, Wo_w, nullptr, out, 0);
}

// round 5
// speedup vs baseline: 1.7300x; 1.1378x over previous
#include <cuda_runtime.h>
#include <cuda_fp16.h>
#include <cstdint>

#define BB 4
#define NN 4096
#define FF 128
#define ALPHA 0.1f
#define KC 64

// ---------------- device scratch ----------------
__device__ float g_w1[FF], g_w2[FF], g_c[2];
__device__ float g_wh1[BB * NN], g_wh2[BB * NN];
__device__ float g_h[BB * NN * FF];                             // 8 MB
__device__ __align__(16) __half g_vph[BB * NN * FF];            // 8 MB fp16 [b][j][f]
__device__ __align__(16) uint32_t g_adjbits[BB * NN * (NN/32)]; // 8.4 MB bitmask

__device__ __forceinline__ float leaky(float x) { return fmaxf(x, ALPHA * x); }

// ---------------- mma.sync helpers ----------------
__device__ __forceinline__ void mma16816(float* d, const uint32_t* a, const uint32_t* b) {
    asm volatile("mma.sync.aligned.m16n8k16.row.col.f32.f16.f16.f32 "
        "{%0,%1,%2,%3},{%4,%5,%6,%7},{%8,%9},{%0,%1,%2,%3};"
        : "+f"(d[0]), "+f"(d[1]), "+f"(d[2]), "+f"(d[3])
        : "r"(a[0]), "r"(a[1]), "r"(a[2]), "r"(a[3]), "r"(b[0]), "r"(b[1]));
}
__device__ __forceinline__ void ldsm_x4(uint32_t* r, uint32_t addr) {
    asm volatile("ldmatrix.sync.aligned.m8n8.x4.shared.b16 {%0,%1,%2,%3},[%4];"
        : "=r"(r[0]), "=r"(r[1]), "=r"(r[2]), "=r"(r[3]) : "r"(addr));
}
__device__ __forceinline__ void ldsm_x4_t(uint32_t* r, uint32_t addr) {
    asm volatile("ldmatrix.sync.aligned.m8n8.x4.trans.shared.b16 {%0,%1,%2,%3},[%4];"
        : "=r"(r[0]), "=r"(r[1]), "=r"(r[2]), "=r"(r[3]) : "r"(addr));
}
__device__ __forceinline__ uint32_t smem_u32(const void* p) {
    uint32_t a;
    asm("{ .reg .u64 t; cvta.to.shared.u64 t, %1; cvt.u32.u64 %0, t; }" : "=r"(a) : "l"(p));
    return a;
}
__device__ __forceinline__ void cp16(uint32_t dst, const void* src) {
    asm volatile("cp.async.cg.shared.global [%0], [%1], 16;" :: "r"(dst), "l"(src) : "memory");
}
#define CP_COMMIT() asm volatile("cp.async.commit_group;" ::: "memory")
#define CP_WAIT0()  asm volatile("cp.async.wait_group 0;" ::: "memory")
__device__ __forceinline__ uint32_t h2u(__half2 h) { return *(uint32_t*)&h; }

// ---------------- kernel 0: pack adj into bitmask --------------------------
// warp -> 8 consecutive 32-bit words (256 adj elements, never straddles a row)
__global__ void __launch_bounds__(256) k_pack(const int* __restrict__ adj) {
    int gw = (blockIdx.x * blockDim.x + threadIdx.x) >> 5;
    int lane = threadIdx.x & 31;
    size_t e0 = (size_t)gw * 256;
    uint32_t wd[8];
    #pragma unroll
    for (int it = 0; it < 8; it++) {
        int a = adj[e0 + it * 32 + lane];
        wd[it] = __ballot_sync(0xffffffffu, a > 0);
    }
    if (lane == 0) {
        uint4* dst = (uint4*)(g_adjbits + (size_t)gw * 8);
        dst[0] = make_uint4(wd[0], wd[1], wd[2], wd[3]);
        dst[1] = make_uint4(wd[4], wd[5], wd[6], wd[7]);
    }
}

// ---------------- kernel 1: fold a into Q/K projections ----------------
__global__ void k_prep(const float* __restrict__ Wq_w, const float* __restrict__ Wq_b,
                       const float* __restrict__ Wk_w, const float* __restrict__ Wk_b,
                       const float* __restrict__ a) {
    int f = threadIdx.x;
    float s1 = 0.f, s2 = 0.f;
    for (int o = 0; o < FF; o++) {
        s1 += Wq_w[o * FF + f] * a[o];
        s2 += Wk_w[o * FF + f] * a[FF + o];
    }
    g_w1[f] = s1; g_w2[f] = s2;
    if (f == 0) {
        float c1 = 0.f, c2 = 0.f;
        for (int o = 0; o < FF; o++) { c1 += Wq_b[o] * a[o]; c2 += Wk_b[o] * a[FF + o]; }
        g_c[0] = c1; g_c[1] = c2;
    }
}

// ---------------- kernel 2: Wh1/Wh2 ----------------
__global__ void k_wh(const float* __restrict__ q, const float* __restrict__ k) {
    int warp = threadIdx.x >> 5, lane = threadIdx.x & 31;
    int row = blockIdx.x * 8 + warp;
    const float* src; const float* w; float c; float* dst; int r;
    if (row < BB * NN) { src = q; w = g_w1; c = g_c[0]; dst = g_wh1; r = row; }
    else               { src = k; w = g_w2; c = g_c[1]; dst = g_wh2; r = row - BB * NN; }
    float4 x  = ((const float4*)(src + (size_t)r * FF))[lane];
    float4 ww = ((const float4*)w)[lane];
    float s = x.x * ww.x + x.y * ww.y + x.z * ww.z + x.w * ww.w;
    #pragma unroll
    for (int o = 16; o > 0; o >>= 1) s += __shfl_xor_sync(0xffffffffu, s, o);
    if (lane == 0) dst[r] = s + c;
}

// ---------------- kernel 3/5: 128x128 projection GEMM ----------------
__global__ void __launch_bounds__(256)
k_gemm128(const float* __restrict__ in, const float* __restrict__ W,
          const float* __restrict__ bias, float* __restrict__ outf, int mode) {
    __shared__ __align__(16) float in_s[32][33];
    __shared__ __align__(16) float wt_s[32][132];
    int t = threadIdx.x;
    int i0 = blockIdx.x * 32;
    int w = t >> 5, l = t & 31;
    float acc[4][4] = {};
    for (int kt = 0; kt < FF; kt += 32) {
        __syncthreads();
        {
            int r = t >> 3, f4 = t & 7;
            float4 v = *(const float4*)(in + (size_t)(i0 + r) * FF + kt + f4 * 4);
            in_s[r][f4 * 4 + 0] = v.x; in_s[r][f4 * 4 + 1] = v.y;
            in_s[r][f4 * 4 + 2] = v.z; in_s[r][f4 * 4 + 3] = v.w;
        }
        #pragma unroll
        for (int kk = 0; kk < 4; kk++) {
            int idx = t + kk * 256;
            int o = idx >> 3, f4 = idx & 7;
            float4 v = *(const float4*)(W + (size_t)o * FF + kt + f4 * 4);
            wt_s[f4 * 4 + 0][o] = v.x; wt_s[f4 * 4 + 1][o] = v.y;
            wt_s[f4 * 4 + 2][o] = v.z; wt_s[f4 * 4 + 3][o] = v.w;
        }
        __syncthreads();
        #pragma unroll
        for (int f = 0; f < 32; f++) {
            float4 wv = *(const float4*)&wt_s[f][l * 4];
            #pragma unroll
            for (int r = 0; r < 4; r++) {
                float iv = in_s[w * 4 + r][f];
                acc[r][0] += iv * wv.x; acc[r][1] += iv * wv.y;
                acc[r][2] += iv * wv.z; acc[r][3] += iv * wv.w;
            }
        }
    }
    float4 bv = make_float4(0.f, 0.f, 0.f, 0.f);
    if (mode == 1) bv = *(const float4*)(bias + l * 4);
    #pragma unroll
    for (int r = 0; r < 4; r++) {
        float4 o4;
        o4.x = acc[r][0] + bv.x; o4.y = acc[r][1] + bv.y;
        o4.z = acc[r][2] + bv.z; o4.w = acc[r][3] + bv.w;
        size_t base = (size_t)(i0 + w * 4 + r) * FF + l * 4;
        if (mode == 0) {
            o4.x = leaky(o4.x); o4.y = leaky(o4.y); o4.z = leaky(o4.z); o4.w = leaky(o4.w);
            *(float4*)(outf + base) = o4;
        } else {
            __half2 h01 = __floats2half2_rn(o4.x, o4.y);
            __half2 h23 = __floats2half2_rn(o4.z, o4.w);
            *(uint2*)(g_vph + base) = make_uint2(h2u(h01), h2u(h23));
        }
    }
}

// ---------------- kernel 4: pipelined masked softmax-agg via mma.sync ------
#define PH_BASE 0            // P hi: 2 x 18432
#define PL_BASE 36864        // P lo: 2 x 18432
#define VH_BASE 73728        // V hi: 2 x 17408
#define WH2_OFF 108544       // wh2 row cache: 16384
#define RS_OFF  124928
#define IV_OFF  125952
#define SM_TOTAL 126464
#define PSTRIDE 144
#define VSTRIDE 272
#define PBUF 18432
#define VBUF 17408

__global__ void __launch_bounds__(256, 1)
k_attn_mma() {
    extern __shared__ char sm[];
    int t = threadIdx.x;
    int lane = t & 31, wid = t >> 5;
    int b = blockIdx.y;
    int it0 = blockIdx.x * 128;

    int mwarp = (wid >> 1) * 32;
    int nwarp = (wid & 1) * 64;

    uint32_t sbase = smem_u32(sm);
    uint32_t aoffH = sbase + PH_BASE + (uint32_t)(mwarp + (lane & 15)) * PSTRIDE + (lane >> 4) * 16;
    uint32_t aoffL = aoffH + (PL_BASE - PH_BASE);
    uint32_t boffH = sbase + VH_BASE + (uint32_t)(lane & 15) * VSTRIDE + (nwarp + (lane >> 4) * 8) * 2;

    // P-gen mapping
    int prow = t >> 1;
    int jh = (t & 1) * 32;
    float wa = g_wh1[b * NN + it0 + prow];
    const uint32_t* maskp = g_adjbits + (size_t)(b * NN + it0 + prow) * (NN / 32) + (t & 1);
    const __half* vph = g_vph + (size_t)b * NN * FF;
    char* pdstH = sm + PH_BASE + prow * PSTRIDE + jh * 2;
    char* pdstL = sm + PL_BASE + prow * PSTRIDE + jh * 2;
    const float* wh2s = (const float*)(sm + WH2_OFF) + jh;

    // V cp.async mapping
    int vr = t >> 2, vs4 = (t & 3) * 4;
    uint32_t vdst = sbase + VH_BASE + vr * VSTRIDE + vs4 * 16;
    const __half* vsrc0 = vph + (size_t)vr * FF + vs4 * 8;

    // stage wh2 for this batch into smem (4096 floats)
    {
        float4* d = (float4*)(sm + WH2_OFF);
        const float4* s = (const float4*)(g_wh2 + b * NN);
        #pragma unroll
        for (int kk = 0; kk < 4; kk++) d[t + kk * 256] = s[t + kk * 256];
    }

    float acc[2][8][4];
    #pragma unroll
    for (int mi = 0; mi < 2; mi++)
        #pragma unroll
        for (int n8 = 0; n8 < 8; n8++)
            #pragma unroll
            for (int x = 0; x < 4; x++) acc[mi][n8][x] = 0.f;
    float rs = 0.f;

    uint2 hiR[8], loR[8];

    auto genP = [&](int j0, uint32_t mask) {
        #pragma unroll
        for (int qq = 0; qq < 8; qq++) {
            float4 e = *(const float4*)(wh2s + j0 + qq * 4);
            float p0 = (mask >> (qq * 4 + 0)) & 1u ? __expf(leaky(wa + e.x)) : 0.f;
            float p1 = (mask >> (qq * 4 + 1)) & 1u ? __expf(leaky(wa + e.y)) : 0.f;
            float p2 = (mask >> (qq * 4 + 2)) & 1u ? __expf(leaky(wa + e.z)) : 0.f;
            float p3 = (mask >> (qq * 4 + 3)) & 1u ? __expf(leaky(wa + e.w)) : 0.f;
            rs += (p0 + p1) + (p2 + p3);
            __half2 h01 = __floats2half2_rn(p0, p1);
            __half2 h23 = __floats2half2_rn(p2, p3);
            float2 f01 = __half22float2(h01), f23 = __half22float2(h23);
            __half2 l01 = __floats2half2_rn(p0 - f01.x, p1 - f01.y);
            __half2 l23 = __floats2half2_rn(p2 - f23.x, p3 - f23.y);
            hiR[qq] = make_uint2(h2u(h01), h2u(h23));
            loR[qq] = make_uint2(h2u(l01), h2u(l23));
        }
    };
    auto storeP = [&](int buf) {
        char* dh = pdstH + buf * PBUF;
        char* dl = pdstL + buf * PBUF;
        #pragma unroll
        for (int qq = 0; qq < 8; qq++) {
            *(uint2*)(dh + qq * 8) = hiR[qq];
            *(uint2*)(dl + qq * 8) = loR[qq];
        }
    };
    auto loadV = [&](int buf, int j0) {
        const __half* s = vsrc0 + (size_t)j0 * FF;
        uint32_t d = vdst + buf * VBUF;
        #pragma unroll
        for (int kk = 0; kk < 4; kk++)
            cp16(d + kk * 16, s + kk * 8);
        CP_COMMIT();
    };

    // ---- prologue ----
    uint32_t mA = __ldg(maskp);           // chunk 0
    uint32_t mB = __ldg(maskp + 2);       // chunk 1
    loadV(0, 0);
    __syncthreads();                      // wh2 staged
    genP(0, mA);
    storeP(0);
    CP_WAIT0();
    __syncthreads();

    for (int c = 0; c < NN / KC; c++) {
        int buf = c & 1, nbuf = buf ^ 1;
        bool has_next = (c + 1) < (NN / KC);
        uint32_t mC = 0;
        if (c + 2 < NN / KC) mC = __ldg(maskp + (size_t)(c + 2) * 2);
        if (has_next) {
            loadV(nbuf, (c + 1) * KC);
            genP((c + 1) * KC, mB);
        }
        // ---- MMA on buffer `buf` ----
        uint32_t pb = aoffH + buf * PBUF;
        uint32_t plb = aoffL + buf * PBUF;
        uint32_t vb = boffH + buf * VBUF;
        #pragma unroll
        for (int kk = 0; kk < 4; kk++) {
            uint32_t ah[2][4], al[2][4];
            ldsm_x4(ah[0], pb + kk * 32);
            ldsm_x4(ah[1], pb + 16 * PSTRIDE + kk * 32);
            ldsm_x4(al[0], plb + kk * 32);
            ldsm_x4(al[1], plb + 16 * PSTRIDE + kk * 32);
            #pragma unroll
            for (int nb = 0; nb < 4; nb++) {
                uint32_t bh[4];
                ldsm_x4_t(bh, vb + kk * 16 * VSTRIDE + nb * 32);
                #pragma unroll
                for (int mi = 0; mi < 2; mi++) {
                    mma16816(acc[mi][nb * 2 + 0], ah[mi], bh + 0);
                    mma16816(acc[mi][nb * 2 + 1], ah[mi], bh + 2);
                    mma16816(acc[mi][nb * 2 + 0], al[mi], bh + 0);
                    mma16816(acc[mi][nb * 2 + 1], al[mi], bh + 2);
                }
            }
        }
        if (has_next) storeP(nbuf);
        mB = mC;
        CP_WAIT0();
        __syncthreads();
    }

    // ---- normalizers ----
    ((float*)(sm + RS_OFF))[t] = rs;
    __syncthreads();
    if (t < 128) {
        float* rss = (float*)(sm + RS_OFF);
        ((float*)(sm + IV_OFF))[t] = 1.0f / (rss[2 * t] + rss[2 * t + 1]);
    }
    __syncthreads();
    const float* inv = (const float*)(sm + IV_OFF);

    // ---- write h ----
    #pragma unroll
    for (int mi = 0; mi < 2; mi++) {
        int r0 = mwarp + mi * 16 + (lane >> 2);
        float iv0 = inv[r0], iv1 = inv[r0 + 8];
        #pragma unroll
        for (int n8 = 0; n8 < 8; n8++) {
            int col = nwarp + n8 * 8 + (lane & 3) * 2;
            float2 v0 = make_float2(acc[mi][n8][0] * iv0, acc[mi][n8][1] * iv0);
            float2 v1 = make_float2(acc[mi][n8][2] * iv1, acc[mi][n8][3] * iv1);
            *(float2*)(g_h + (size_t)(b * NN + it0 + r0) * FF + col) = v0;
            *(float2*)(g_h + (size_t)(b * NN + it0 + r0 + 8) * FF + col) = v1;
        }
    }
}

// ---------------- launch ----------------
extern "C" void kernel_launch(void* const* d_in, const int* in_sizes, int n_in,
                              void* d_out, int out_size) {
    const float* q    = (const float*)d_in[0];
    const float* k    = (const float*)d_in[1];
    const float* v    = (const float*)d_in[2];
    const int*   adj  = (const int*)  d_in[3];
    const float* Wq_w = (const float*)d_in[4];
    const float* Wq_b = (const float*)d_in[5];
    const float* Wk_w = (const float*)d_in[6];
    const float* Wk_b = (const float*)d_in[7];
    const float* Wv_w = (const float*)d_in[8];
    const float* Wv_b = (const float*)d_in[9];
    const float* a    = (const float*)d_in[10];
    const float* Wo_w = (const float*)d_in[11];
    float* out = (float*)d_out;

    void* h_ptr = nullptr;
    cudaGetSymbolAddress(&h_ptr, g_h);

    cudaFuncSetAttribute(k_attn_mma, cudaFuncAttributeMaxDynamicSharedMemorySize, SM_TOTAL);

    // pack adj: 64Mi elements / 256 per warp / 8 warps per block
    k_pack<<<(BB * NN * NN) / (256 * 8), 256>>>(adj);
    k_prep<<<1, 128>>>(Wq_w, Wq_b, Wk_w, Wk_b, a);
    k_wh<<<(2 * BB * NN) / 8, 256>>>(q, k);
    k_gemm128<<<BB * NN / 32, 256>>>(v, Wv_w, Wv_b, nullptr, 1);
    {
        dim3 grid(NN / 128, BB);
        k_attn_mma<<<grid, 256, SM_TOTAL>>>();
    }
    k_gemm128<<<BB * NN / 32, 256>>>((const float*)h_ptr, Wo_w, nullptr, out, 0);
}

// round 6
// speedup vs baseline: 2.1271x; 1.2296x over previous
#include <cuda_runtime.h>
#include <cuda_fp16.h>
#include <cstdint>

#define BB 4
#define NN 4096
#define FF 128
#define ALPHA 0.1f
#define KC 64

// ---------------- device scratch ----------------
__device__ float g_w1[FF], g_w2[FF], g_c[2];
__device__ float g_wh1[BB * NN], g_wh2[BB * NN];
__device__ float g_h[BB * NN * FF];                             // 8 MB
__device__ __align__(16) __half g_vph[BB * NN * FF];            // 4 MB fp16 [b][j][f]
__device__ __align__(16) uint32_t g_adjbits[BB * NN * (NN/32)]; // 8.4 MB bitmask

__device__ __forceinline__ float leaky(float x) { return fmaxf(x, ALPHA * x); }

// ---------------- mma.sync helpers ----------------
__device__ __forceinline__ void mma16816(float* d, const uint32_t* a, const uint32_t* b) {
    asm volatile("mma.sync.aligned.m16n8k16.row.col.f32.f16.f16.f32 "
        "{%0,%1,%2,%3},{%4,%5,%6,%7},{%8,%9},{%0,%1,%2,%3};"
        : "+f"(d[0]), "+f"(d[1]), "+f"(d[2]), "+f"(d[3])
        : "r"(a[0]), "r"(a[1]), "r"(a[2]), "r"(a[3]), "r"(b[0]), "r"(b[1]));
}
__device__ __forceinline__ void ldsm_x4(uint32_t* r, uint32_t addr) {
    asm volatile("ldmatrix.sync.aligned.m8n8.x4.shared.b16 {%0,%1,%2,%3},[%4];"
        : "=r"(r[0]), "=r"(r[1]), "=r"(r[2]), "=r"(r[3]) : "r"(addr));
}
__device__ __forceinline__ void ldsm_x4_t(uint32_t* r, uint32_t addr) {
    asm volatile("ldmatrix.sync.aligned.m8n8.x4.trans.shared.b16 {%0,%1,%2,%3},[%4];"
        : "=r"(r[0]), "=r"(r[1]), "=r"(r[2]), "=r"(r[3]) : "r"(addr));
}
__device__ __forceinline__ uint32_t smem_u32(const void* p) {
    uint32_t a;
    asm("{ .reg .u64 t; cvta.to.shared.u64 t, %1; cvt.u32.u64 %0, t; }" : "=r"(a) : "l"(p));
    return a;
}
__device__ __forceinline__ void cp16(uint32_t dst, const void* src) {
    asm volatile("cp.async.cg.shared.global [%0], [%1], 16;" :: "r"(dst), "l"(src) : "memory");
}
#define CP_COMMIT() asm volatile("cp.async.commit_group;" ::: "memory")
#define CP_WAIT0()  asm volatile("cp.async.wait_group 0;" ::: "memory")
__device__ __forceinline__ uint32_t h2u(__half2 h) { return *(uint32_t*)&h; }

// ---------------- kernel 0: pack adj into bitmask --------------------------
__global__ void __launch_bounds__(256) k_pack(const int* __restrict__ adj) {
    int gw = (blockIdx.x * blockDim.x + threadIdx.x) >> 5;
    int lane = threadIdx.x & 31;
    size_t e0 = (size_t)gw * 256;
    uint32_t wd[8];
    #pragma unroll
    for (int it = 0; it < 8; it++) {
        int a = adj[e0 + it * 32 + lane];
        wd[it] = __ballot_sync(0xffffffffu, a > 0);
    }
    if (lane == 0) {
        uint4* dst = (uint4*)(g_adjbits + (size_t)gw * 8);
        dst[0] = make_uint4(wd[0], wd[1], wd[2], wd[3]);
        dst[1] = make_uint4(wd[4], wd[5], wd[6], wd[7]);
    }
}

// ---------------- kernel 1: fold a into Q/K projections ----------------
__global__ void k_prep(const float* __restrict__ Wq_w, const float* __restrict__ Wq_b,
                       const float* __restrict__ Wk_w, const float* __restrict__ Wk_b,
                       const float* __restrict__ a) {
    int f = threadIdx.x;
    float s1 = 0.f, s2 = 0.f;
    for (int o = 0; o < FF; o++) {
        s1 += Wq_w[o * FF + f] * a[o];
        s2 += Wk_w[o * FF + f] * a[FF + o];
    }
    g_w1[f] = s1; g_w2[f] = s2;
    if (f == 0) {
        float c1 = 0.f, c2 = 0.f;
        for (int o = 0; o < FF; o++) { c1 += Wq_b[o] * a[o]; c2 += Wk_b[o] * a[FF + o]; }
        g_c[0] = c1; g_c[1] = c2;
    }
}

// ---------------- kernel 2: Wh1/Wh2 ----------------
__global__ void k_wh(const float* __restrict__ q, const float* __restrict__ k) {
    int warp = threadIdx.x >> 5, lane = threadIdx.x & 31;
    int row = blockIdx.x * 8 + warp;
    const float* src; const float* w; float c; float* dst; int r;
    if (row < BB * NN) { src = q; w = g_w1; c = g_c[0]; dst = g_wh1; r = row; }
    else               { src = k; w = g_w2; c = g_c[1]; dst = g_wh2; r = row - BB * NN; }
    float4 x  = ((const float4*)(src + (size_t)r * FF))[lane];
    float4 ww = ((const float4*)w)[lane];
    float s = x.x * ww.x + x.y * ww.y + x.z * ww.z + x.w * ww.w;
    #pragma unroll
    for (int o = 16; o > 0; o >>= 1) s += __shfl_xor_sync(0xffffffffu, s, o);
    if (lane == 0) dst[r] = s + c;
}

// ---------------- kernel 3/5: 128x128 projection GEMM ----------------
__global__ void __launch_bounds__(256)
k_gemm128(const float* __restrict__ in, const float* __restrict__ W,
          const float* __restrict__ bias, float* __restrict__ outf, int mode) {
    __shared__ __align__(16) float in_s[32][33];
    __shared__ __align__(16) float wt_s[32][132];
    int t = threadIdx.x;
    int i0 = blockIdx.x * 32;
    int w = t >> 5, l = t & 31;
    float acc[4][4] = {};
    for (int kt = 0; kt < FF; kt += 32) {
        __syncthreads();
        {
            int r = t >> 3, f4 = t & 7;
            float4 v = *(const float4*)(in + (size_t)(i0 + r) * FF + kt + f4 * 4);
            in_s[r][f4 * 4 + 0] = v.x; in_s[r][f4 * 4 + 1] = v.y;
            in_s[r][f4 * 4 + 2] = v.z; in_s[r][f4 * 4 + 3] = v.w;
        }
        #pragma unroll
        for (int kk = 0; kk < 4; kk++) {
            int idx = t + kk * 256;
            int o = idx >> 3, f4 = idx & 7;
            float4 v = *(const float4*)(W + (size_t)o * FF + kt + f4 * 4);
            wt_s[f4 * 4 + 0][o] = v.x; wt_s[f4 * 4 + 1][o] = v.y;
            wt_s[f4 * 4 + 2][o] = v.z; wt_s[f4 * 4 + 3][o] = v.w;
        }
        __syncthreads();
        #pragma unroll
        for (int f = 0; f < 32; f++) {
            float4 wv = *(const float4*)&wt_s[f][l * 4];
            #pragma unroll
            for (int r = 0; r < 4; r++) {
                float iv = in_s[w * 4 + r][f];
                acc[r][0] += iv * wv.x; acc[r][1] += iv * wv.y;
                acc[r][2] += iv * wv.z; acc[r][3] += iv * wv.w;
            }
        }
    }
    float4 bv = make_float4(0.f, 0.f, 0.f, 0.f);
    if (mode == 1) bv = *(const float4*)(bias + l * 4);
    #pragma unroll
    for (int r = 0; r < 4; r++) {
        float4 o4;
        o4.x = acc[r][0] + bv.x; o4.y = acc[r][1] + bv.y;
        o4.z = acc[r][2] + bv.z; o4.w = acc[r][3] + bv.w;
        size_t base = (size_t)(i0 + w * 4 + r) * FF + l * 4;
        if (mode == 0) {
            o4.x = leaky(o4.x); o4.y = leaky(o4.y); o4.z = leaky(o4.z); o4.w = leaky(o4.w);
            *(float4*)(outf + base) = o4;
        } else {
            __half2 h01 = __floats2half2_rn(o4.x, o4.y);
            __half2 h23 = __floats2half2_rn(o4.z, o4.w);
            *(uint2*)(g_vph + base) = make_uint2(h2u(h01), h2u(h23));
        }
    }
}

// ---------------- kernel 4: pipelined masked softmax-agg (512 threads) -----
#define PH_BASE 0            // P hi: 2 x 18432
#define PL_BASE 36864        // P lo: 2 x 18432
#define VH_BASE 73728        // V hi: 2 x 17408
#define WH2_OFF 108544       // wh2 row cache: 16384
#define RS_OFF  124928       // 512 floats
#define IV_OFF  126976       // 128 floats
#define SM_TOTAL 127488
#define PSTRIDE 144
#define VSTRIDE 272
#define PBUF 18432
#define VBUF 17408

__global__ void __launch_bounds__(512, 1)
k_attn_mma() {
    extern __shared__ char sm[];
    int t = threadIdx.x;
    int lane = t & 31, wid = t >> 5;
    int b = blockIdx.y;
    int it0 = blockIdx.x * 128;

    int mwarp = (wid >> 2) * 32;     // 4 warp-rows x 32 rows
    int nwarp = (wid & 3) * 32;      // 4 warp-cols x 32 cols

    uint32_t sbase = smem_u32(sm);
    uint32_t aoffH = sbase + PH_BASE + (uint32_t)(mwarp + (lane & 15)) * PSTRIDE + (lane >> 4) * 16;
    uint32_t aoffL = aoffH + (PL_BASE - PH_BASE);
    uint32_t boffH = sbase + VH_BASE + (uint32_t)(lane & 15) * VSTRIDE + (nwarp + (lane >> 4) * 8) * 2;

    // P-gen mapping: 4 threads per row, 16 j's each
    int prow = t >> 2;
    int pq = t & 3;                      // quarter of the 64-j chunk
    float wa = g_wh1[b * NN + it0 + prow];
    const uint32_t* maskp = g_adjbits + (size_t)(b * NN + it0 + prow) * (NN / 32) + (pq >> 1);
    int msh = (pq & 1) * 16;
    const __half* vph = g_vph + (size_t)b * NN * FF;
    char* pdstH = sm + PH_BASE + prow * PSTRIDE + pq * 32;
    char* pdstL = sm + PL_BASE + prow * PSTRIDE + pq * 32;
    const float* wh2s = (const float*)(sm + WH2_OFF) + pq * 16;

    // V cp.async mapping: 8 threads per row, 2 x 16B each
    int vr = t >> 3, vs = t & 7;
    uint32_t vdst = sbase + VH_BASE + vr * VSTRIDE + vs * 32;
    const __half* vsrc0 = vph + (size_t)vr * FF + vs * 16;

    // stage wh2 for this batch (4096 floats, 2 float4/thread)
    {
        float4* d = (float4*)(sm + WH2_OFF);
        const float4* s = (const float4*)(g_wh2 + b * NN);
        d[t] = s[t];
        d[t + 512] = s[t + 512];
    }

    float acc[2][4][4];
    #pragma unroll
    for (int mi = 0; mi < 2; mi++)
        #pragma unroll
        for (int n8 = 0; n8 < 4; n8++)
            #pragma unroll
            for (int x = 0; x < 4; x++) acc[mi][n8][x] = 0.f;
    float rs = 0.f;

    uint2 hiR[4], loR[4];

    auto genP = [&](int j0, uint32_t mask16) {
        #pragma unroll
        for (int qq = 0; qq < 4; qq++) {
            float4 e = *(const float4*)(wh2s + j0 + qq * 4);
            float p0 = (mask16 >> (qq * 4 + 0)) & 1u ? __expf(leaky(wa + e.x)) : 0.f;
            float p1 = (mask16 >> (qq * 4 + 1)) & 1u ? __expf(leaky(wa + e.y)) : 0.f;
            float p2 = (mask16 >> (qq * 4 + 2)) & 1u ? __expf(leaky(wa + e.z)) : 0.f;
            float p3 = (mask16 >> (qq * 4 + 3)) & 1u ? __expf(leaky(wa + e.w)) : 0.f;
            rs += (p0 + p1) + (p2 + p3);
            __half2 h01 = __floats2half2_rn(p0, p1);
            __half2 h23 = __floats2half2_rn(p2, p3);
            float2 f01 = __half22float2(h01), f23 = __half22float2(h23);
            __half2 l01 = __floats2half2_rn(p0 - f01.x, p1 - f01.y);
            __half2 l23 = __floats2half2_rn(p2 - f23.x, p3 - f23.y);
            hiR[qq] = make_uint2(h2u(h01), h2u(h23));
            loR[qq] = make_uint2(h2u(l01), h2u(l23));
        }
    };
    auto storeP = [&](int buf) {
        char* dh = pdstH + buf * PBUF;
        char* dl = pdstL + buf * PBUF;
        #pragma unroll
        for (int qq = 0; qq < 4; qq++) {
            *(uint2*)(dh + qq * 8) = hiR[qq];
            *(uint2*)(dl + qq * 8) = loR[qq];
        }
    };
    auto loadV = [&](int buf, int j0) {
        const __half* s = vsrc0 + (size_t)j0 * FF;
        uint32_t d = vdst + buf * VBUF;
        cp16(d, s);
        cp16(d + 16, s + 8);
        CP_COMMIT();
    };

    // ---- prologue ----
    uint32_t wA = __ldg(maskp);
    uint32_t wB = __ldg(maskp + 2);
    uint32_t mA = (wA >> msh) & 0xffffu;
    uint32_t mB = (wB >> msh) & 0xffffu;
    loadV(0, 0);
    __syncthreads();                      // wh2 staged
    genP(0, mA);
    storeP(0);
    CP_WAIT0();
    __syncthreads();

    for (int c = 0; c < NN / KC; c++) {
        int buf = c & 1, nbuf = buf ^ 1;
        bool has_next = (c + 1) < (NN / KC);
        uint32_t mC = 0;
        if (c + 2 < NN / KC)
            mC = (__ldg(maskp + (size_t)(c + 2) * 2) >> msh) & 0xffffu;
        if (has_next) {
            loadV(nbuf, (c + 1) * KC);
            genP((c + 1) * KC, mB);
        }
        // ---- MMA on buffer `buf` ----
        uint32_t pb = aoffH + buf * PBUF;
        uint32_t plb = aoffL + buf * PBUF;
        uint32_t vb = boffH + buf * VBUF;
        #pragma unroll
        for (int kk = 0; kk < 4; kk++) {
            uint32_t ah[2][4], al[2][4];
            ldsm_x4(ah[0], pb + kk * 32);
            ldsm_x4(ah[1], pb + 16 * PSTRIDE + kk * 32);
            ldsm_x4(al[0], plb + kk * 32);
            ldsm_x4(al[1], plb + 16 * PSTRIDE + kk * 32);
            #pragma unroll
            for (int nb = 0; nb < 2; nb++) {
                uint32_t bh[4];
                ldsm_x4_t(bh, vb + kk * 16 * VSTRIDE + nb * 32);
                #pragma unroll
                for (int mi = 0; mi < 2; mi++) {
                    mma16816(acc[mi][nb * 2 + 0], ah[mi], bh + 0);
                    mma16816(acc[mi][nb * 2 + 1], ah[mi], bh + 2);
                    mma16816(acc[mi][nb * 2 + 0], al[mi], bh + 0);
                    mma16816(acc[mi][nb * 2 + 1], al[mi], bh + 2);
                }
            }
        }
        if (has_next) storeP(nbuf);
        mB = mC;
        CP_WAIT0();
        __syncthreads();
    }

    // ---- normalizers: 4 partial sums per row ----
    ((float*)(sm + RS_OFF))[t] = rs;
    __syncthreads();
    if (t < 128) {
        const float* rss = (const float*)(sm + RS_OFF) + t * 4;
        ((float*)(sm + IV_OFF))[t] = 1.0f / ((rss[0] + rss[1]) + (rss[2] + rss[3]));
    }
    __syncthreads();
    const float* inv = (const float*)(sm + IV_OFF);

    // ---- write h ----
    #pragma unroll
    for (int mi = 0; mi < 2; mi++) {
        int r0 = mwarp + mi * 16 + (lane >> 2);
        float iv0 = inv[r0], iv1 = inv[r0 + 8];
        #pragma unroll
        for (int n8 = 0; n8 < 4; n8++) {
            int col = nwarp + n8 * 8 + (lane & 3) * 2;
            float2 v0 = make_float2(acc[mi][n8][0] * iv0, acc[mi][n8][1] * iv0);
            float2 v1 = make_float2(acc[mi][n8][2] * iv1, acc[mi][n8][3] * iv1);
            *(float2*)(g_h + (size_t)(b * NN + it0 + r0) * FF + col) = v0;
            *(float2*)(g_h + (size_t)(b * NN + it0 + r0 + 8) * FF + col) = v1;
        }
    }
}

// ---------------- launch ----------------
extern "C" void kernel_launch(void* const* d_in, const int* in_sizes, int n_in,
                              void* d_out, int out_size) {
    const float* q    = (const float*)d_in[0];
    const float* k    = (const float*)d_in[1];
    const float* v    = (const float*)d_in[2];
    const int*   adj  = (const int*)  d_in[3];
    const float* Wq_w = (const float*)d_in[4];
    const float* Wq_b = (const float*)d_in[5];
    const float* Wk_w = (const float*)d_in[6];
    const float* Wk_b = (const float*)d_in[7];
    const float* Wv_w = (const float*)d_in[8];
    const float* Wv_b = (const float*)d_in[9];
    const float* a    = (const float*)d_in[10];
    const float* Wo_w = (const float*)d_in[11];
    float* out = (float*)d_out;

    void* h_ptr = nullptr;
    cudaGetSymbolAddress(&h_ptr, g_h);

    cudaFuncSetAttribute(k_attn_mma, cudaFuncAttributeMaxDynamicSharedMemorySize, SM_TOTAL);

    k_pack<<<(BB * NN * NN) / (256 * 8), 256>>>(adj);
    k_prep<<<1, 128>>>(Wq_w, Wq_b, Wk_w, Wk_b, a);
    k_wh<<<(2 * BB * NN) / 8, 256>>>(q, k);
    k_gemm128<<<BB * NN / 32, 256>>>(v, Wv_w, Wv_b, nullptr, 1);
    {
        dim3 grid(NN / 128, BB);
        k_attn_mma<<<grid, 512, SM_TOTAL>>>();
    }
    k_gemm128<<<BB * NN / 32, 256>>>((const float*)h_ptr, Wo_w, nullptr, out, 0);
}

// round 7
// speedup vs baseline: 2.4525x; 1.1530x over previous
#include <cuda_runtime.h>
#include <cuda_fp16.h>
#include <cstdint>

#define BB 4
#define NN 4096
#define FF 128
#define ALPHA 0.1f
#define KC 64

// ---------------- device scratch ----------------
__device__ float g_w1[FF], g_w2[FF], g_c[2];
__device__ float g_wh1[BB * NN], g_wh2[BB * NN];
__device__ float g_h[BB * NN * FF];                             // 8 MB
__device__ __align__(16) __half g_vph[BB * NN * FF];            // 4 MB fp16 [b][j][f]
__device__ __align__(16) uint32_t g_adjbits[BB * NN * (NN/32)]; // 8.4 MB bitmask

__device__ __forceinline__ float leaky(float x) { return fmaxf(x, ALPHA * x); }

// ---------------- mma.sync helpers ----------------
__device__ __forceinline__ void mma16816(float* d, const uint32_t* a, const uint32_t* b) {
    asm volatile("mma.sync.aligned.m16n8k16.row.col.f32.f16.f16.f32 "
        "{%0,%1,%2,%3},{%4,%5,%6,%7},{%8,%9},{%0,%1,%2,%3};"
        : "+f"(d[0]), "+f"(d[1]), "+f"(d[2]), "+f"(d[3])
        : "r"(a[0]), "r"(a[1]), "r"(a[2]), "r"(a[3]), "r"(b[0]), "r"(b[1]));
}
__device__ __forceinline__ void ldsm_x4(uint32_t* r, uint32_t addr) {
    asm volatile("ldmatrix.sync.aligned.m8n8.x4.shared.b16 {%0,%1,%2,%3},[%4];"
        : "=r"(r[0]), "=r"(r[1]), "=r"(r[2]), "=r"(r[3]) : "r"(addr));
}
__device__ __forceinline__ void ldsm_x4_t(uint32_t* r, uint32_t addr) {
    asm volatile("ldmatrix.sync.aligned.m8n8.x4.trans.shared.b16 {%0,%1,%2,%3},[%4];"
        : "=r"(r[0]), "=r"(r[1]), "=r"(r[2]), "=r"(r[3]) : "r"(addr));
}
__device__ __forceinline__ uint32_t smem_u32(const void* p) {
    uint32_t a;
    asm("{ .reg .u64 t; cvta.to.shared.u64 t, %1; cvt.u32.u64 %0, t; }" : "=r"(a) : "l"(p));
    return a;
}
__device__ __forceinline__ void cp16(uint32_t dst, const void* src) {
    asm volatile("cp.async.cg.shared.global [%0], [%1], 16;" :: "r"(dst), "l"(src) : "memory");
}
#define CP_COMMIT() asm volatile("cp.async.commit_group;" ::: "memory")
#define CP_WAIT0()  asm volatile("cp.async.wait_group 0;" ::: "memory")
__device__ __forceinline__ uint32_t h2u(__half2 h) { return *(uint32_t*)&h; }

// ---------------- kernel 0: pack adj into bitmask (vectorized) -------------
// thread -> 8 consecutive elements (2x int4), byte-shuffle pack into words
__global__ void __launch_bounds__(256) k_pack(const int* __restrict__ adj) {
    int t = blockIdx.x * 256 + threadIdx.x;
    const int4* p = (const int4*)adj + (size_t)t * 2;
    int4 a = p[0], b = p[1];
    uint32_t bits =
        (uint32_t)(a.x != 0)        | ((uint32_t)(a.y != 0) << 1) |
        ((uint32_t)(a.z != 0) << 2) | ((uint32_t)(a.w != 0) << 3) |
        ((uint32_t)(b.x != 0) << 4) | ((uint32_t)(b.y != 0) << 5) |
        ((uint32_t)(b.z != 0) << 6) | ((uint32_t)(b.w != 0) << 7);
    int lane = threadIdx.x & 31;
    uint32_t my = bits << ((lane & 3) * 8);
    my |= __shfl_xor_sync(0xffffffffu, my, 1);
    my |= __shfl_xor_sync(0xffffffffu, my, 2);
    if ((lane & 3) == 0) g_adjbits[t >> 2] = my;
}

// ---------------- kernel 1: fold a into Q/K projections ----------------
__global__ void k_prep(const float* __restrict__ Wq_w, const float* __restrict__ Wq_b,
                       const float* __restrict__ Wk_w, const float* __restrict__ Wk_b,
                       const float* __restrict__ a) {
    int f = threadIdx.x;
    float s1 = 0.f, s2 = 0.f;
    for (int o = 0; o < FF; o++) {
        s1 += Wq_w[o * FF + f] * a[o];
        s2 += Wk_w[o * FF + f] * a[FF + o];
    }
    g_w1[f] = s1; g_w2[f] = s2;
    if (f == 0) {
        float c1 = 0.f, c2 = 0.f;
        for (int o = 0; o < FF; o++) { c1 += Wq_b[o] * a[o]; c2 += Wk_b[o] * a[FF + o]; }
        g_c[0] = c1; g_c[1] = c2;
    }
}

// ---------------- kernel 2: Wh1/Wh2 ----------------
__global__ void k_wh(const float* __restrict__ q, const float* __restrict__ k) {
    int warp = threadIdx.x >> 5, lane = threadIdx.x & 31;
    int row = blockIdx.x * 8 + warp;
    const float* src; const float* w; float c; float* dst; int r;
    if (row < BB * NN) { src = q; w = g_w1; c = g_c[0]; dst = g_wh1; r = row; }
    else               { src = k; w = g_w2; c = g_c[1]; dst = g_wh2; r = row - BB * NN; }
    float4 x  = ((const float4*)(src + (size_t)r * FF))[lane];
    float4 ww = ((const float4*)w)[lane];
    float s = x.x * ww.x + x.y * ww.y + x.z * ww.z + x.w * ww.w;
    #pragma unroll
    for (int o = 16; o > 0; o >>= 1) s += __shfl_xor_sync(0xffffffffu, s, o);
    if (lane == 0) dst[r] = s + c;
}

// ---------------- kernel 3/5: 128x128 projection GEMM ----------------
__global__ void __launch_bounds__(256)
k_gemm128(const float* __restrict__ in, const float* __restrict__ W,
          const float* __restrict__ bias, float* __restrict__ outf, int mode) {
    __shared__ __align__(16) float in_s[32][33];
    __shared__ __align__(16) float wt_s[32][132];
    int t = threadIdx.x;
    int i0 = blockIdx.x * 32;
    int w = t >> 5, l = t & 31;
    float acc[4][4] = {};
    for (int kt = 0; kt < FF; kt += 32) {
        __syncthreads();
        {
            int r = t >> 3, f4 = t & 7;
            float4 v = *(const float4*)(in + (size_t)(i0 + r) * FF + kt + f4 * 4);
            in_s[r][f4 * 4 + 0] = v.x; in_s[r][f4 * 4 + 1] = v.y;
            in_s[r][f4 * 4 + 2] = v.z; in_s[r][f4 * 4 + 3] = v.w;
        }
        #pragma unroll
        for (int kk = 0; kk < 4; kk++) {
            int idx = t + kk * 256;
            int o = idx >> 3, f4 = idx & 7;
            float4 v = *(const float4*)(W + (size_t)o * FF + kt + f4 * 4);
            wt_s[f4 * 4 + 0][o] = v.x; wt_s[f4 * 4 + 1][o] = v.y;
            wt_s[f4 * 4 + 2][o] = v.z; wt_s[f4 * 4 + 3][o] = v.w;
        }
        __syncthreads();
        #pragma unroll
        for (int f = 0; f < 32; f++) {
            float4 wv = *(const float4*)&wt_s[f][l * 4];
            #pragma unroll
            for (int r = 0; r < 4; r++) {
                float iv = in_s[w * 4 + r][f];
                acc[r][0] += iv * wv.x; acc[r][1] += iv * wv.y;
                acc[r][2] += iv * wv.z; acc[r][3] += iv * wv.w;
            }
        }
    }
    float4 bv = make_float4(0.f, 0.f, 0.f, 0.f);
    if (mode == 1) bv = *(const float4*)(bias + l * 4);
    #pragma unroll
    for (int r = 0; r < 4; r++) {
        float4 o4;
        o4.x = acc[r][0] + bv.x; o4.y = acc[r][1] + bv.y;
        o4.z = acc[r][2] + bv.z; o4.w = acc[r][3] + bv.w;
        size_t base = (size_t)(i0 + w * 4 + r) * FF + l * 4;
        if (mode == 0) {
            o4.x = leaky(o4.x); o4.y = leaky(o4.y); o4.z = leaky(o4.z); o4.w = leaky(o4.w);
            *(float4*)(outf + base) = o4;
        } else {
            __half2 h01 = __floats2half2_rn(o4.x, o4.y);
            __half2 h23 = __floats2half2_rn(o4.z, o4.w);
            *(uint2*)(g_vph + base) = make_uint2(h2u(h01), h2u(h23));
        }
    }
}

// ---------------- kernel 4: pipelined masked softmax-agg (512 threads) -----
#define PH_BASE 0            // P hi: 2 x 18432
#define VH_BASE 36864        // V hi: 2 x 17408
#define WH2_OFF 71680        // wh2 row cache: 16384
#define RS_OFF  88064        // 512 floats
#define IV_OFF  90112        // 128 floats
#define SM_TOTAL 90624
#define PSTRIDE 144
#define VSTRIDE 272
#define PBUF 18432
#define VBUF 17408

__global__ void __launch_bounds__(512, 1)
k_attn_mma() {
    extern __shared__ char sm[];
    int t = threadIdx.x;
    int lane = t & 31, wid = t >> 5;
    int b = blockIdx.y;
    int it0 = blockIdx.x * 128;

    int mwarp = (wid >> 2) * 32;     // 4 warp-rows x 32 rows
    int nwarp = (wid & 3) * 32;      // 4 warp-cols x 32 cols

    uint32_t sbase = smem_u32(sm);
    uint32_t aoffH = sbase + PH_BASE + (uint32_t)(mwarp + (lane & 15)) * PSTRIDE + (lane >> 4) * 16;
    uint32_t boffH = sbase + VH_BASE + (uint32_t)(lane & 15) * VSTRIDE + (nwarp + (lane >> 4) * 8) * 2;

    // P-gen mapping: 4 threads per row, 16 j's each
    int prow = t >> 2;
    int pq = t & 3;
    float wa = g_wh1[b * NN + it0 + prow];
    const uint32_t* maskp = g_adjbits + (size_t)(b * NN + it0 + prow) * (NN / 32) + (pq >> 1);
    int msh = (pq & 1) * 16;
    const __half* vph = g_vph + (size_t)b * NN * FF;
    char* pdstH = sm + PH_BASE + prow * PSTRIDE + pq * 32;
    const float* wh2s = (const float*)(sm + WH2_OFF) + pq * 16;

    // V cp.async mapping: 8 threads per row, 2 x 16B each
    int vr = t >> 3, vs = t & 7;
    uint32_t vdst = sbase + VH_BASE + vr * VSTRIDE + vs * 32;
    const __half* vsrc0 = vph + (size_t)vr * FF + vs * 16;

    // stage wh2 for this batch (4096 floats, 2 float4/thread)
    {
        float4* d = (float4*)(sm + WH2_OFF);
        const float4* s = (const float4*)(g_wh2 + b * NN);
        d[t] = s[t];
        d[t + 512] = s[t + 512];
    }

    float acc[2][4][4];
    #pragma unroll
    for (int mi = 0; mi < 2; mi++)
        #pragma unroll
        for (int n8 = 0; n8 < 4; n8++)
            #pragma unroll
            for (int x = 0; x < 4; x++) acc[mi][n8][x] = 0.f;
    float rs = 0.f;

    uint2 hiR[4];

    auto genP = [&](int j0, uint32_t mask16) {
        #pragma unroll
        for (int qq = 0; qq < 4; qq++) {
            float4 e = *(const float4*)(wh2s + j0 + qq * 4);
            float p0 = (mask16 >> (qq * 4 + 0)) & 1u ? __expf(leaky(wa + e.x)) : 0.f;
            float p1 = (mask16 >> (qq * 4 + 1)) & 1u ? __expf(leaky(wa + e.y)) : 0.f;
            float p2 = (mask16 >> (qq * 4 + 2)) & 1u ? __expf(leaky(wa + e.z)) : 0.f;
            float p3 = (mask16 >> (qq * 4 + 3)) & 1u ? __expf(leaky(wa + e.w)) : 0.f;
            rs += (p0 + p1) + (p2 + p3);
            __half2 h01 = __floats2half2_rn(p0, p1);
            __half2 h23 = __floats2half2_rn(p2, p3);
            hiR[qq] = make_uint2(h2u(h01), h2u(h23));
        }
    };
    auto storeP = [&](int buf) {
        char* dh = pdstH + buf * PBUF;
        #pragma unroll
        for (int qq = 0; qq < 4; qq++)
            *(uint2*)(dh + qq * 8) = hiR[qq];
    };
    auto loadV = [&](int buf, int j0) {
        const __half* s = vsrc0 + (size_t)j0 * FF;
        uint32_t d = vdst + buf * VBUF;
        cp16(d, s);
        cp16(d + 16, s + 8);
        CP_COMMIT();
    };

    // ---- prologue ----
    uint32_t wA = __ldg(maskp);
    uint32_t wB = __ldg(maskp + 2);
    uint32_t mA = (wA >> msh) & 0xffffu;
    uint32_t mB = (wB >> msh) & 0xffffu;
    loadV(0, 0);
    __syncthreads();                      // wh2 staged
    genP(0, mA);
    storeP(0);
    CP_WAIT0();
    __syncthreads();

    for (int c = 0; c < NN / KC; c++) {
        int buf = c & 1, nbuf = buf ^ 1;
        bool has_next = (c + 1) < (NN / KC);
        uint32_t mC = 0;
        if (c + 2 < NN / KC)
            mC = (__ldg(maskp + (size_t)(c + 2) * 2) >> msh) & 0xffffu;
        if (has_next) {
            loadV(nbuf, (c + 1) * KC);
            genP((c + 1) * KC, mB);
        }
        // ---- MMA on buffer `buf` ----
        uint32_t pb = aoffH + buf * PBUF;
        uint32_t vb = boffH + buf * VBUF;
        #pragma unroll
        for (int kk = 0; kk < 4; kk++) {
            uint32_t ah[2][4];
            ldsm_x4(ah[0], pb + kk * 32);
            ldsm_x4(ah[1], pb + 16 * PSTRIDE + kk * 32);
            #pragma unroll
            for (int nb = 0; nb < 2; nb++) {
                uint32_t bh[4];
                ldsm_x4_t(bh, vb + kk * 16 * VSTRIDE + nb * 32);
                #pragma unroll
                for (int mi = 0; mi < 2; mi++) {
                    mma16816(acc[mi][nb * 2 + 0], ah[mi], bh + 0);
                    mma16816(acc[mi][nb * 2 + 1], ah[mi], bh + 2);
                }
            }
        }
        if (has_next) storeP(nbuf);
        mB = mC;
        CP_WAIT0();
        __syncthreads();
    }

    // ---- normalizers: 4 partial sums per row ----
    ((float*)(sm + RS_OFF))[t] = rs;
    __syncthreads();
    if (t < 128) {
        const float* rss = (const float*)(sm + RS_OFF) + t * 4;
        ((float*)(sm + IV_OFF))[t] = 1.0f / ((rss[0] + rss[1]) + (rss[2] + rss[3]));
    }
    __syncthreads();
    const float* inv = (const float*)(sm + IV_OFF);

    // ---- write h ----
    #pragma unroll
    for (int mi = 0; mi < 2; mi++) {
        int r0 = mwarp + mi * 16 + (lane >> 2);
        float iv0 = inv[r0], iv1 = inv[r0 + 8];
        #pragma unroll
        for (int n8 = 0; n8 < 4; n8++) {
            int col = nwarp + n8 * 8 + (lane & 3) * 2;
            float2 v0 = make_float2(acc[mi][n8][0] * iv0, acc[mi][n8][1] * iv0);
            float2 v1 = make_float2(acc[mi][n8][2] * iv1, acc[mi][n8][3] * iv1);
            *(float2*)(g_h + (size_t)(b * NN + it0 + r0) * FF + col) = v0;
            *(float2*)(g_h + (size_t)(b * NN + it0 + r0 + 8) * FF + col) = v1;
        }
    }
}

// ---------------- launch ----------------
extern "C" void kernel_launch(void* const* d_in, const int* in_sizes, int n_in,
                              void* d_out, int out_size) {
    const float* q    = (const float*)d_in[0];
    const float* k    = (const float*)d_in[1];
    const float* v    = (const float*)d_in[2];
    const int*   adj  = (const int*)  d_in[3];
    const float* Wq_w = (const float*)d_in[4];
    const float* Wq_b = (const float*)d_in[5];
    const float* Wk_w = (const float*)d_in[6];
    const float* Wk_b = (const float*)d_in[7];
    const float* Wv_w = (const float*)d_in[8];
    const float* Wv_b = (const float*)d_in[9];
    const float* a    = (const float*)d_in[10];
    const float* Wo_w = (const float*)d_in[11];
    float* out = (float*)d_out;

    void* h_ptr = nullptr;
    cudaGetSymbolAddress(&h_ptr, g_h);

    cudaFuncSetAttribute(k_attn_mma, cudaFuncAttributeMaxDynamicSharedMemorySize, SM_TOTAL);

    k_pack<<<(BB * NN * NN) / (256 * 8), 256>>>(adj);
    k_prep<<<1, 128>>>(Wq_w, Wq_b, Wk_w, Wk_b, a);
    k_wh<<<(2 * BB * NN) / 8, 256>>>(q, k);
    k_gemm128<<<BB * NN / 32, 256>>>(v, Wv_w, Wv_b, nullptr, 1);
    {
        dim3 grid(NN / 128, BB);
        k_attn_mma<<<grid, 512, SM_TOTAL>>>();
    }
    k_gemm128<<<BB * NN / 32, 256>>>((const float*)h_ptr, Wo_w, nullptr, out, 0);
}